// round 8
// baseline (speedup 1.0000x reference)
#include <cuda_runtime.h>
#include <cuda_bf16.h>
#include <stdint.h>

// KAN_6597069767329: per-input-feature cubic B-spline least squares.
//   x [N,64] f32, y [N,64,16] f32, grid uniform (hardcoded)
//   out [16,64,11] f32 : out[o,i,k] = solve(A_i^T A_i, A_i^T B_i)[k,o]

#define IN_F   64
#define OUT_F  16
#define KB     11
#define NCH    37            // 32 pairs * 37 = 1184 = 8 * 148 SMs exactly
#define MCH    8
#define TILE   256
#define NMAX   100352

typedef unsigned long long ull;

__device__ float g_xT[IN_F * NMAX];
// [feat][chunk][sh(2)][oh(2)][o(8)][k(12)]
__device__ float g_pAtB[IN_F * NCH * 2 * 2 * 8 * 12];
// [feat][mchunk][56]
__device__ float g_pMom[IN_F * MCH * 56];

// ---- smem layout (floats) for accum ----------------------------------------
#define YS_STRIDE 36
#define YS_BUF    (TILE * YS_STRIDE)            // 9216 floats / buf
#define YS_NBUF   4
#define BP_OFF    (YS_NBUF * YS_BUF)            // 36864 ; [f][buf][q(3)][256] ull
#define BP_FLOATS (2 * 2 * 3 * TILE * 2)        // 6144
#define META_OFF  (BP_OFF + BP_FLOATS)          // [f][buf][256] int = 1024
#define SCR_OFF   (META_OFF + 1024)             // cnt[2][8][4] + offs[2][8][4] = 128
#define SMEM_FLOATS (SCR_OFF + 128)             // 44160 floats = 176640 B

// ---- helpers ---------------------------------------------------------------
__device__ __forceinline__ void fma2(ull &acc, ull a, ull b) {
    asm("fma.rn.f32x2 %0, %1, %2, %0;" : "+l"(acc) : "l"(a), "l"(b));
}
__device__ __forceinline__ ull bcast2(float v) {
    ull r; unsigned int u = __float_as_uint(v);
    asm("mov.b64 %0, {%1, %1};" : "=l"(r) : "r"(u));
    return r;
}
__device__ __forceinline__ ull pack2(float lo, float hi) {
    ull r;
    asm("mov.b64 %0, {%1, %2};" : "=l"(r) : "r"(__float_as_uint(lo)), "r"(__float_as_uint(hi)));
    return r;
}
__device__ __forceinline__ ull wred2(ull v) {
#pragma unroll
    for (int m = 16; m > 0; m >>= 1) {
        ull o = __shfl_xor_sync(0xffffffffu, v, m);
        asm("add.rn.f32x2 %0, %0, %1;" : "+l"(v) : "l"(o));
    }
    return v;
}
__device__ __forceinline__ unsigned smem_u32(const void* p) {
    return (unsigned)__cvta_generic_to_shared(p);
}
__device__ __forceinline__ void cp16(unsigned dst, const void* src) {
    asm volatile("cp.async.cg.shared.global [%0], [%1], 16;" :: "r"(dst), "l"(src));
}
__device__ __forceinline__ void cp_commit() {
    asm volatile("cp.async.commit_group;");
}
__device__ __forceinline__ void cp_wait2() {
    asm volatile("cp.async.wait_group 2;");
}

// sparse frame: 3 k-pairs starting at pair P, 8 outputs
template <int P>
__device__ __forceinline__ void frame(ull* acc, ull c0, ull c1, ull c2, const ull* yB) {
#pragma unroll
    for (int o = 0; o < 8; o++) {
        fma2(acc[(P + 0) * 8 + o], c0, yB[o]);
        fma2(acc[(P + 1) * 8 + o], c1, yB[o]);
        fma2(acc[(P + 2) * 8 + o], c2, yB[o]);
    }
}
__device__ __forceinline__ void frame_dispatch(int pp, ull* acc, ull c0, ull c1, ull c2,
                                               const ull* yB) {
    switch (pp) {
        case 0: frame<0>(acc, c0, c1, c2, yB); break;
        case 1: frame<1>(acc, c0, c1, c2, yB); break;
        case 2: frame<2>(acc, c0, c1, c2, yB); break;
        default: frame<3>(acc, c0, c1, c2, yB); break;
    }
}

// ---- phase 0: transpose x [N,64] -> xT [64,N] ------------------------------
__global__ void transpose_kernel(const float* __restrict__ x, int N) {
    __shared__ float tile[32][33];
    int n0 = blockIdx.x * 32;
    int c0 = blockIdx.y * 32;
#pragma unroll
    for (int r = 0; r < 4; r++) {
        int row = threadIdx.y + r * 8;
        int n = n0 + row;
        if (n < N) tile[row][threadIdx.x] = x[(size_t)n * IN_F + c0 + threadIdx.x];
    }
    __syncthreads();
#pragma unroll
    for (int r = 0; r < 4; r++) {
        int f = threadIdx.y + r * 8;
        int n = n0 + threadIdx.x;
        if (n < N) g_xT[(size_t)(c0 + f) * N + n] = tile[threadIdx.x][f];
    }
}

// ---- phase 0b: per-cell u-power moments ------------------------------------
__global__ __launch_bounds__(256) void moments_kernel(int N) {
    const int chunk = blockIdx.x;
    const int feat  = blockIdx.y;
    const int t = threadIdx.x;
    const int warp = t >> 5, lane = t & 31;

    const int per  = (N + MCH - 1) / MCH;
    const int s_lo = chunk * per;
    const int s_hi = min(N, s_lo + per);

    float mom[8][7];
#pragma unroll
    for (int jc = 0; jc < 8; jc++)
#pragma unroll
        for (int p = 0; p < 7; p++) mom[jc][p] = 0.f;

    const float* xT = g_xT + (size_t)feat * N;
    for (int s = s_lo + t; s < s_hi; s += 256) {
        float xv = __ldg(xT + s);
        float tt = (xv + 1.0f) * 4.0f;
        int j = (int)floorf(tt);
        j = max(0, min(7, j));
        float u = tt - (float)j;
        float up[7];
        up[0] = 1.f;
#pragma unroll
        for (int p = 1; p < 7; p++) up[p] = up[p - 1] * u;
#pragma unroll
        for (int jc = 0; jc < 8; jc++) {
            float sel = (jc == j) ? 1.f : 0.f;
#pragma unroll
            for (int p = 0; p < 7; p++) mom[jc][p] += sel * up[p];
        }
    }

    __shared__ float red[8 * 57];
#pragma unroll
    for (int jc = 0; jc < 8; jc++)
#pragma unroll
        for (int p = 0; p < 7; p++) {
            float v = mom[jc][p];
#pragma unroll
            for (int m = 16; m > 0; m >>= 1)
                v += __shfl_xor_sync(0xffffffffu, v, m);
            if (lane == 0) red[warp * 57 + jc * 7 + p] = v;
        }
    __syncthreads();
    if (t < 56) {
        float s = 0.f;
#pragma unroll
        for (int w = 0; w < 8; w++) s += red[w * 57 + t];
        g_pMom[((size_t)feat * MCH + chunk) * 56 + t] = s;
    }
}

// ---- phase 1: AtB accumulation (bucket-sorted sparse frames) ----------------
__global__ __launch_bounds__(256, 1) void accum_kernel(const float* __restrict__ y, int N) {
    extern __shared__ float sm[];
    float* Ys  = sm;                        // 4 bufs [256][36]
    ull*   BP  = (ull*)(sm + BP_OFF);       // [f][buf][q][256]
    int*   MT  = (int*)(sm + META_OFF);     // [f][buf][256] : idx | p<<8
    int*   CNT = (int*)(sm + SCR_OFF);      // [f][w][b] (f*32+w*4+b)
    int*   OFFS = CNT + 64;

    const int pair  = blockIdx.y;
    const int chunk = blockIdx.x;
    const int i0 = pair * 2;
    const int t = threadIdx.x;
    const int warp = t >> 5, lane = t & 31;
    const unsigned lmlt = (1u << lane) - 1u;
    const int fw = warp & 1;
    const int oh = (warp >> 1) & 1;
    const int sh = warp >> 2;

    const int per  = (N + NCH - 1) / NCH;
    const int s_lo = chunk * per;
    const int s_hi = min(N, s_lo + per);
    const int nt   = (s_hi - s_lo + TILE - 1) / TILE;

    const float* xT0 = g_xT + (size_t)i0 * N;
    const float* xT1 = g_xT + (size_t)(i0 + 1) * N;

    ull acc[48];
#pragma unroll
    for (int q = 0; q < 48; q++) acc[q] = 0ull;

    // sort + stage basis pairs for tile ti into buffer bb (2-deep)
    auto stage_sort = [&](int ti, int bb, float xv0, float xv1, bool valid) {
        int p_f[2], rank_f[2];
        ull pr[2][3];
#pragma unroll
        for (int f = 0; f < 2; f++) {
            int p = 3;
            ull b0 = 0, b1 = 0, b2 = 0;
            if (valid) {
                float xv = f ? xv1 : xv0;
                float tt = (xv + 1.0f) * 4.0f;
                int j = (int)floorf(tt);
                j = max(0, min(7, j));
                float u = tt - (float)j;
                float um = 1.0f - u;
                float u2 = u * u, u3 = u2 * u;
                float um3 = um * um * um;
                const float c6 = 1.0f / 6.0f;
                float w0 = um3 * c6;
                float w1 = (3.0f * u3 - 6.0f * u2 + 4.0f) * c6;
                float w2 = (-3.0f * u3 + 3.0f * u2 + 3.0f * u + 1.0f) * c6;
                float w3 = u3 * c6;
                p = j >> 1;
                if (j & 1) {
                    b0 = pack2(0.f, w0); b1 = pack2(w1, w2); b2 = pack2(w3, 0.f);
                } else {
                    b0 = pack2(w0, w1); b1 = pack2(w2, w3); b2 = 0ull;
                }
            }
            unsigned m0 = __ballot_sync(0xffffffffu, p == 0);
            unsigned m1 = __ballot_sync(0xffffffffu, p == 1);
            unsigned m2 = __ballot_sync(0xffffffffu, p == 2);
            unsigned m3 = __ballot_sync(0xffffffffu, p == 3);
            unsigned mp = (p == 0) ? m0 : (p == 1) ? m1 : (p == 2) ? m2 : m3;
            rank_f[f] = __popc(mp & lmlt);
            p_f[f] = p;
            if (lane < 4) {
                unsigned mb = (lane == 0) ? m0 : (lane == 1) ? m1 : (lane == 2) ? m2 : m3;
                CNT[f * 32 + warp * 4 + lane] = __popc(mb);
            }
            pr[f][0] = b0; pr[f][1] = b1; pr[f][2] = b2;
        }
        __syncthreads();
        if (warp == 0) {
#pragma unroll
            for (int f = 0; f < 2; f++) {
                int b = lane >> 3, w = lane & 7;     // bucket-major order
                int v = CNT[f * 32 + w * 4 + b];
                int incl = v;
#pragma unroll
                for (int d = 1; d < 32; d <<= 1) {
                    int n = __shfl_up_sync(0xffffffffu, incl, d);
                    if (lane >= d) incl += n;
                }
                OFFS[f * 32 + w * 4 + b] = incl - v;
            }
        }
        __syncthreads();
#pragma unroll
        for (int f = 0; f < 2; f++) {
            int pos = OFFS[f * 32 + warp * 4 + p_f[f]] + rank_f[f];
            int base = (f * 2 + bb) * 3 * TILE;
            BP[base + 0 * TILE + pos] = pr[f][0];
            BP[base + 1 * TILE + pos] = pr[f][1];
            BP[base + 2 * TILE + pos] = pr[f][2];
            MT[(f * 2 + bb) * TILE + pos] = t | (p_f[f] << 8);
        }
    };

    auto issue_y = [&](int ti) {
        int b = ti % YS_NBUF;
        int s0 = s_lo + ti * TILE;
#pragma unroll
        for (int e = t; e < TILE * 8; e += 256) {
            int sloc = e >> 3, q = e & 7;
            int s = s0 + sloc;
            float* dstp = Ys + b * YS_BUF + sloc * YS_STRIDE + q * 4;
            if (s < s_hi)
                cp16(smem_u32(dstp), y + ((size_t)s * IN_F + i0) * OUT_F + q * 4);
            else
                *(float4*)dstp = make_float4(0.f, 0.f, 0.f, 0.f);
        }
    };

    // prolog
    {
        int s = s_lo + t;
        bool v = s < s_hi;
        float a0 = v ? __ldg(xT0 + s) : 0.f;
        float a1 = v ? __ldg(xT1 + s) : 0.f;
        stage_sort(0, 0, a0, a1, v);
    }
    float pf0 = 0.f, pf1 = 0.f;
    bool pfv = false;
    if (nt > 1) {
        int s = s_lo + TILE + t;
        pfv = s < s_hi;
        if (pfv) { pf0 = __ldg(xT0 + s); pf1 = __ldg(xT1 + s); }
    }
    issue_y(0); cp_commit();
    if (nt > 1) issue_y(1);
    cp_commit();
    if (nt > 2) issue_y(2);
    cp_commit();

    for (int i = 0; i < nt; i++) {
        const int b = i % YS_NBUF, b2 = i & 1;
        cp_wait2();
        __syncthreads();
        if (i + 3 < nt) issue_y(i + 3);
        cp_commit();

        const ull* BPc = BP + (fw * 2 + b2) * 3 * TILE;
        const int* MTc = MT + (fw * 2 + b2) * TILE;
        const float* YsC = Ys + b * YS_BUF;
#pragma unroll
        for (int jj = 0; jj < 4; jj++) {
            int sl = sh * 128 + jj * 32 + lane;
            int meta = MTc[sl];
            int idx = meta & 255;
            int p   = meta >> 8;
            ull c0 = BPc[0 * TILE + sl];
            ull c1 = BPc[1 * TILE + sl];
            ull c2 = BPc[2 * TILE + sl];
            const float4* yrow = (const float4*)(YsC + idx * YS_STRIDE + fw * 16 + oh * 8);
            float4 ya = yrow[0];
            float4 yb = yrow[1];
            ull yB[8];
            yB[0] = bcast2(ya.x); yB[1] = bcast2(ya.y);
            yB[2] = bcast2(ya.z); yB[3] = bcast2(ya.w);
            yB[4] = bcast2(yb.x); yB[5] = bcast2(yb.y);
            yB[6] = bcast2(yb.z); yB[7] = bcast2(yb.w);
            int plo = __shfl_sync(0xffffffffu, p, 0);
            int phi = __shfl_sync(0xffffffffu, p, 31);
            if (plo == phi) {
                frame_dispatch(plo, acc, c0, c1, c2, yB);
            } else {
                for (int pp = plo; pp <= phi; pp++) {
                    ull z0 = (p == pp) ? c0 : 0ull;
                    ull z1 = (p == pp) ? c1 : 0ull;
                    ull z2 = (p == pp) ? c2 : 0ull;
                    frame_dispatch(pp, acc, z0, z1, z2, yB);
                }
            }
        }

        if (i + 1 < nt) stage_sort(i + 1, (i + 1) & 1, pf0, pf1, pfv);
        if (i + 2 < nt) {
            int s = s_lo + (i + 2) * TILE + t;
            pfv = s < s_hi;
            pf0 = pfv ? __ldg(xT0 + s) : 0.f;
            pf1 = pfv ? __ldg(xT1 + s) : 0.f;
        } else {
            pfv = false;
        }
    }

#pragma unroll
    for (int q = 0; q < 48; q++) acc[q] = wred2(acc[q]);
    if (lane == 0) {
        size_t base = ((((size_t)(i0 + fw) * NCH + chunk) * 2 + sh) * 2 + oh) * 96;
#pragma unroll
        for (int o = 0; o < 8; o++)
#pragma unroll
            for (int kp = 0; kp < 6; kp++)
                *(ull*)(g_pAtB + base + o * 12 + 2 * kp) = acc[kp * 8 + o];
    }
}

// triangle index (a <= b)
__device__ __forceinline__ int tidx(int a, int b) {
    return a * KB - (a * (a - 1)) / 2 + (b - a);
}

__device__ __constant__ double CAD[4][4] = {
    {1.0, -3.0,  3.0, -1.0},
    {4.0,  0.0, -6.0,  3.0},
    {1.0,  3.0,  3.0, -3.0},
    {0.0,  0.0,  0.0,  1.0}
};

// ---- phase 2: parallel reduction + parallel-column float Cholesky ----------
__global__ __launch_bounds__(256) void solve_kernel(float* __restrict__ out) {
    const int i = blockIdx.x;
    const int t = threadIdx.x;
    __shared__ float  sAtB[12][OUT_F];
    __shared__ double sS[56];
    __shared__ double sAtAd[66];
    __shared__ float  sL[66];
    __shared__ float  sLinv[KB];

    if (t < 192) {
        int k = t % 12, o = t / 12;
        int ohh = o >> 3, oo = o & 7;
        const float* p = g_pAtB + (size_t)i * (NCH * 2 * 2 * 96)
                       + ohh * 96 + oo * 12 + k;
        float s = 0.f;
#pragma unroll
        for (int cs = 0; cs < NCH * 2; cs++)
            s += p[(size_t)cs * 192];
        sAtB[k][o] = s;
    } else if (t < 248) {
        int p = t - 192;
        const float* q = g_pMom + (size_t)i * (MCH * 56) + p;
        double s = 0.0;
#pragma unroll
        for (int c = 0; c < MCH; c++)
            s += (double)q[c * 56];
        sS[p] = s;
    }
    __syncthreads();

    if (t < 66) {
        int p = t, r = 0;
        while (p >= KB - r) { p -= KB - r; r++; }
        int cc = r + p;
        double v0 = 0.0, v1 = 0.0, v2 = 0.0, v3 = 0.0;
        for (int j = 0; j < 8; j++) {
            int a = r - j, b = cc - j;
            if (a >= 0 && a < 4 && b >= 0 && b < 4) {
#pragma unroll
                for (int q1 = 0; q1 < 4; q1++) {
                    double cb = CAD[b][q1];
                    v0 += CAD[a][0] * cb * sS[j * 7 + 0 + q1];
                    v1 += CAD[a][1] * cb * sS[j * 7 + 1 + q1];
                    v2 += CAD[a][2] * cb * sS[j * 7 + 2 + q1];
                    v3 += CAD[a][3] * cb * sS[j * 7 + 3 + q1];
                }
            }
        }
        sAtAd[t] = ((v0 + v1) + (v2 + v3)) / 36.0;
    }
    __syncthreads();

    // parallel-column Cholesky
    for (int j = 0; j < KB; j++) {
        if (t == 0) {
            float d = (float)sAtAd[tidx(j, j)];
            for (int m = 0; m < j; m++) { float v = sL[tidx(m, j)]; d -= v * v; }
            d = sqrtf(d);
            sL[tidx(j, j)] = d;
            sLinv[j] = 1.0f / d;
        }
        __syncthreads();
        if (t > j && t < KB) {
            float s = (float)sAtAd[tidx(j, t)];
            for (int m = 0; m < j; m++) s -= sL[tidx(m, t)] * sL[tidx(m, j)];
            sL[tidx(j, t)] = s * sLinv[j];
        }
        __syncthreads();
    }

    if (t < OUT_F) {
        const int o = t;
        float z[KB], X[KB];
#pragma unroll
        for (int r = 0; r < KB; r++) {
            float s = sAtB[r][o];
#pragma unroll
            for (int m = 0; m < KB; m++) if (m < r) s -= sL[tidx(m, r)] * z[m];
            z[r] = s * sLinv[r];
        }
#pragma unroll
        for (int r = KB - 1; r >= 0; r--) {
            float s = z[r];
#pragma unroll
            for (int m = KB - 1; m >= 0; m--) if (m > r) s -= sL[tidx(r, m)] * X[m];
            X[r] = s * sLinv[r];
            out[(size_t)o * (IN_F * KB) + i * KB + r] = X[r];
        }
    }
}

extern "C" void kernel_launch(void* const* d_in, const int* in_sizes, int n_in,
                              void* d_out, int out_size) {
    const float* x = (const float*)d_in[0];
    const float* y = (const float*)d_in[1];
    (void)n_in; (void)out_size;
    float* out = (float*)d_out;
    int N = in_sizes[0] / IN_F;

    cudaFuncSetAttribute(accum_kernel,
                         cudaFuncAttributeMaxDynamicSharedMemorySize,
                         SMEM_FLOATS * (int)sizeof(float));

    dim3 tgrid((N + 31) / 32, IN_F / 32);
    transpose_kernel<<<tgrid, dim3(32, 8)>>>(x, N);

    moments_kernel<<<dim3(MCH, IN_F), 256>>>(N);

    accum_kernel<<<dim3(NCH, 32), 256, SMEM_FLOATS * (int)sizeof(float)>>>(y, N);

    solve_kernel<<<IN_F, 256>>>(out);
}

// round 9
// speedup vs baseline: 1.6337x; 1.6337x over previous
#include <cuda_runtime.h>
#include <cuda_bf16.h>
#include <stdint.h>

// KAN_6597069767329: per-input-feature cubic B-spline least squares.
//   x [N,64] f32, y [N,64,16] f32, grid uniform (hardcoded)
//   out [16,64,11] f32 : out[o,i,k] = solve(A_i^T A_i, A_i^T B_i)[k,o]

#define IN_F   64
#define OUT_F  16
#define KB     11
#define NCH    74            // 32 pairs * 74 = 2368 = 16 * 148 SMs exactly
#define MCH    8
#define TILE   128
#define NMAX   100352

typedef unsigned long long ull;

__device__ float g_xT[IN_F * NMAX];
// [feat][chunk][oh(2)][o(8)][k(12)]
__device__ float g_pAtB[IN_F * NCH * 2 * 8 * 12];
// [feat][mchunk][56]
__device__ float g_pMom[IN_F * MCH * 56];

// ---- smem layout (floats) for accum ----------------------------------------
#define YS_STRIDE 36
#define YS_BUF    (TILE * YS_STRIDE)            // 4608 floats / buf (18 KB)
#define YS_NBUF   4
#define BS_OFF    (YS_NBUF * YS_BUF)            // 18432
#define BS_STRIDE 14
#define BS_FEAT   (TILE * BS_STRIDE)            // 1792
#define BS_BUF    (2 * BS_FEAT)                 // 3584 (2 features)
#define SMEM_FLOATS (BS_OFF + 2 * BS_BUF)       // 25600 floats = 102400 B -> 2 blocks/SM

// ---- helpers ---------------------------------------------------------------
__device__ __forceinline__ void fma2(ull &acc, ull a, ull b) {
    asm("fma.rn.f32x2 %0, %1, %2, %0;" : "+l"(acc) : "l"(a), "l"(b));
}
__device__ __forceinline__ ull bcast2(float v) {
    ull r; unsigned int u = __float_as_uint(v);
    asm("mov.b64 %0, {%1, %1};" : "=l"(r) : "r"(u));
    return r;
}
__device__ __forceinline__ ull wred2(ull v) {
#pragma unroll
    for (int m = 16; m > 0; m >>= 1) {
        ull o = __shfl_xor_sync(0xffffffffu, v, m);
        asm("add.rn.f32x2 %0, %0, %1;" : "+l"(v) : "l"(o));
    }
    return v;
}
__device__ __forceinline__ unsigned smem_u32(const void* p) {
    return (unsigned)__cvta_generic_to_shared(p);
}
__device__ __forceinline__ void cp16(unsigned dst, const void* src) {
    asm volatile("cp.async.cg.shared.global [%0], [%1], 16;" :: "r"(dst), "l"(src));
}
__device__ __forceinline__ void cp_commit() {
    asm volatile("cp.async.commit_group;");
}
__device__ __forceinline__ void cp_wait2() {
    asm volatile("cp.async.wait_group 2;");
}

// ---- phase 0: transpose x [N,64] -> xT [64,N] ------------------------------
__global__ void transpose_kernel(const float* __restrict__ x, int N) {
    __shared__ float tile[32][33];
    int n0 = blockIdx.x * 32;
    int c0 = blockIdx.y * 32;
#pragma unroll
    for (int r = 0; r < 4; r++) {
        int row = threadIdx.y + r * 8;
        int n = n0 + row;
        if (n < N) tile[row][threadIdx.x] = x[(size_t)n * IN_F + c0 + threadIdx.x];
    }
    __syncthreads();
#pragma unroll
    for (int r = 0; r < 4; r++) {
        int f = threadIdx.y + r * 8;
        int n = n0 + threadIdx.x;
        if (n < N) g_xT[(size_t)(c0 + f) * N + n] = tile[threadIdx.x][f];
    }
}

// ---- phase 0b: per-cell u-power moments ------------------------------------
__global__ __launch_bounds__(256) void moments_kernel(int N) {
    const int chunk = blockIdx.x;
    const int feat  = blockIdx.y;
    const int t = threadIdx.x;
    const int warp = t >> 5, lane = t & 31;

    const int per  = (N + MCH - 1) / MCH;
    const int s_lo = chunk * per;
    const int s_hi = min(N, s_lo + per);

    float mom[8][7];
#pragma unroll
    for (int jc = 0; jc < 8; jc++)
#pragma unroll
        for (int p = 0; p < 7; p++) mom[jc][p] = 0.f;

    const float* xT = g_xT + (size_t)feat * N;
    // vectorized: 4 samples per iteration per thread
    for (int s4 = s_lo + t * 4; s4 < s_hi; s4 += 256 * 4) {
        float4 xv4;
        if (s4 + 3 < s_hi) {
            xv4 = *(const float4*)(xT + s4);
        } else {
            xv4.x = xT[s4];
            xv4.y = (s4 + 1 < s_hi) ? xT[s4 + 1] : -2.f;
            xv4.z = (s4 + 2 < s_hi) ? xT[s4 + 2] : -2.f;
            xv4.w = (s4 + 3 < s_hi) ? xT[s4 + 3] : -2.f;
        }
        float xs[4] = {xv4.x, xv4.y, xv4.z, xv4.w};
#pragma unroll
        for (int e = 0; e < 4; e++) {
            float xv = xs[e];
            bool ok = xv >= -1.5f;            // skip padding sentinel
            float tt = (xv + 1.0f) * 4.0f;
            int j = (int)floorf(tt);
            j = max(0, min(7, j));
            float u = tt - (float)j;
            float up[7];
            up[0] = ok ? 1.f : 0.f;
#pragma unroll
            for (int p = 1; p < 7; p++) up[p] = up[p - 1] * u;
#pragma unroll
            for (int jc = 0; jc < 8; jc++) {
                float sel = (jc == j) ? 1.f : 0.f;
#pragma unroll
                for (int p = 0; p < 7; p++) mom[jc][p] += sel * up[p];
            }
        }
    }

    __shared__ float red[8 * 57];
#pragma unroll
    for (int jc = 0; jc < 8; jc++)
#pragma unroll
        for (int p = 0; p < 7; p++) {
            float v = mom[jc][p];
#pragma unroll
            for (int m = 16; m > 0; m >>= 1)
                v += __shfl_xor_sync(0xffffffffu, v, m);
            if (lane == 0) red[warp * 57 + jc * 7 + p] = v;
        }
    __syncthreads();
    if (t < 56) {
        float s = 0.f;
#pragma unroll
        for (int w = 0; w < 8; w++) s += red[w * 57 + t];
        g_pMom[((size_t)feat * MCH + chunk) * 56 + t] = s;
    }
}

// ---- phase 1: AtB accumulation (k-split warps, 2 blocks/SM) -----------------
__global__ __launch_bounds__(256, 2) void accum_kernel(const float* __restrict__ y, int N) {
    extern __shared__ float sm[];
    float* Ys = sm;                 // 4 bufs [128][36]
    float* Bs = sm + BS_OFF;        // 2 bufs [2 feat][128][14]

    const int pair  = blockIdx.y;
    const int chunk = blockIdx.x;
    const int i0 = pair * 2;
    const int t = threadIdx.x;
    const int warp = t >> 5, lane = t & 31;
    const int fw = warp & 1;        // feature within pair
    const int oh = (warp >> 1) & 1; // output half
    const int kh = warp >> 2;       // k half (pairs 3kh..3kh+2)

    const int per  = (N + NCH - 1) / NCH;
    const int s_lo = chunk * per;
    const int s_hi = min(N, s_lo + per);
    const int nt   = (s_hi - s_lo + TILE - 1) / TILE;

    const float* xT0 = g_xT + (size_t)i0 * N;
    const float* xT1 = g_xT + (size_t)(i0 + 1) * N;

    ull acc[24];                    // [kp(3)][o(8)]
#pragma unroll
    for (int q = 0; q < 24; q++) acc[q] = 0ull;

    auto stage_basis_reg = [&](int bb, float xv0, float xv1, bool valid) {
        if (t >= TILE) return;
        float* row0 = Bs + bb * BS_BUF + t * BS_STRIDE;
        float* row1 = row0 + BS_FEAT;
        float2 z2 = make_float2(0.f, 0.f);
#pragma unroll
        for (int q = 0; q < 6; q++) { ((float2*)row0)[q] = z2; ((float2*)row1)[q] = z2; }
        if (valid) {
#pragma unroll
            for (int f = 0; f < 2; f++) {
                float xv = f ? xv1 : xv0;
                float* row = f ? row1 : row0;
                float tt = (xv + 1.0f) * 4.0f;
                int j = (int)floorf(tt);
                j = max(0, min(7, j));
                float u = tt - (float)j;
                float um = 1.0f - u;
                float u2 = u * u, u3 = u2 * u;
                float um3 = um * um * um;
                const float c6 = 1.0f / 6.0f;
                row[j]     = um3 * c6;
                row[j + 1] = (3.0f * u3 - 6.0f * u2 + 4.0f) * c6;
                row[j + 2] = (-3.0f * u3 + 3.0f * u2 + 3.0f * u + 1.0f) * c6;
                row[j + 3] = u3 * c6;
            }
        }
    };
    auto issue_y = [&](int ti) {
        int b = ti % YS_NBUF;
        int s0 = s_lo + ti * TILE;
#pragma unroll
        for (int e = t; e < TILE * 8; e += 256) {
            int sloc = e >> 3, q = e & 7;
            int s = s0 + sloc;
            float* dstp = Ys + b * YS_BUF + sloc * YS_STRIDE + q * 4;
            if (s < s_hi)
                cp16(smem_u32(dstp), y + ((size_t)s * IN_F + i0) * OUT_F + q * 4);
            else
                *(float4*)dstp = make_float4(0.f, 0.f, 0.f, 0.f);
        }
    };

    // prolog: basis tile 0 direct, prefetch tile 1
    {
        int s = s_lo + t;
        bool v = (t < TILE) && (s < s_hi);
        float a0 = v ? __ldg(xT0 + s) : 0.f;
        float a1 = v ? __ldg(xT1 + s) : 0.f;
        stage_basis_reg(0, a0, a1, v);
    }
    float pf0 = 0.f, pf1 = 0.f;
    bool pfv = false;
    if (nt > 1 && t < TILE) {
        int s = s_lo + TILE + t;
        pfv = s < s_hi;
        if (pfv) { pf0 = __ldg(xT0 + s); pf1 = __ldg(xT1 + s); }
    }
    issue_y(0); cp_commit();
    if (nt > 1) issue_y(1);
    cp_commit();
    if (nt > 2) issue_y(2);
    cp_commit();

    for (int i = 0; i < nt; i++) {
        const int b = i % YS_NBUF, b2 = i & 1;
        cp_wait2();
        __syncthreads();
        if (i + 3 < nt) issue_y(i + 3);
        cp_commit();

        const float* BsC = Bs + b2 * BS_BUF + fw * BS_FEAT + 6 * kh;
        const float* YsC = Ys + b * YS_BUF + fw * 16 + oh * 8;
#pragma unroll
        for (int jj = 0; jj < 4; jj++) {
            int sl = jj * 32 + lane;
            const float* brow = BsC + sl * BS_STRIDE;
            const float4* yrow = (const float4*)(YsC + sl * YS_STRIDE);
            float4 ya = yrow[0];
            float4 yb = yrow[1];
            ull b2v[3];
#pragma unroll
            for (int kp = 0; kp < 3; kp++)
                b2v[kp] = *(const ull*)(brow + 2 * kp);
            ull yB[8];
            yB[0] = bcast2(ya.x); yB[1] = bcast2(ya.y);
            yB[2] = bcast2(ya.z); yB[3] = bcast2(ya.w);
            yB[4] = bcast2(yb.x); yB[5] = bcast2(yb.y);
            yB[6] = bcast2(yb.z); yB[7] = bcast2(yb.w);
#pragma unroll
            for (int kp = 0; kp < 3; kp++)
#pragma unroll
                for (int o = 0; o < 8; o++)
                    fma2(acc[kp * 8 + o], b2v[kp], yB[o]);
        }

        if (i + 1 < nt) stage_basis_reg((i + 1) & 1, pf0, pf1, pfv);
        if (i + 2 < nt && t < TILE) {
            int s = s_lo + (i + 2) * TILE + t;
            pfv = s < s_hi;
            pf0 = pfv ? __ldg(xT0 + s) : 0.f;
            pf1 = pfv ? __ldg(xT1 + s) : 0.f;
        } else {
            pfv = false;
        }
    }

    // reduce + write: warp owns k-pairs 3kh..3kh+2 for (feat=i0+fw, oh)
#pragma unroll
    for (int q = 0; q < 24; q++) acc[q] = wred2(acc[q]);
    if (lane == 0) {
        size_t base = (((size_t)(i0 + fw) * NCH + chunk) * 2 + oh) * 96;
#pragma unroll
        for (int o = 0; o < 8; o++)
#pragma unroll
            for (int kp = 0; kp < 3; kp++)
                *(ull*)(g_pAtB + base + o * 12 + 6 * kh + 2 * kp) = acc[kp * 8 + o];
    }
}

// triangle index (a <= b)
__device__ __forceinline__ int tidx(int a, int b) {
    return a * KB - (a * (a - 1)) / 2 + (b - a);
}

__device__ __constant__ double CAD[4][4] = {
    {1.0, -3.0,  3.0, -1.0},
    {4.0,  0.0, -6.0,  3.0},
    {1.0,  3.0,  3.0, -3.0},
    {0.0,  0.0,  0.0,  1.0}
};

// ---- phase 2: parallel reduction + parallel-column float Cholesky ----------
__global__ __launch_bounds__(256) void solve_kernel(float* __restrict__ out) {
    const int i = blockIdx.x;
    const int t = threadIdx.x;
    __shared__ float  sAtB[12][OUT_F];
    __shared__ double sS[56];
    __shared__ double sAtAd[66];
    __shared__ float  sL[66];
    __shared__ float  sLinv[KB];

    if (t < 192) {
        int k = t % 12, o = t / 12;
        int ohh = o >> 3, oo = o & 7;
        const float* p = g_pAtB + (size_t)i * (NCH * 2 * 96)
                       + ohh * 96 + oo * 12 + k;
        float s = 0.f;
#pragma unroll
        for (int c = 0; c < NCH; c++)
            s += p[(size_t)c * 192];
        sAtB[k][o] = s;
    } else if (t < 248) {
        int p = t - 192;
        const float* q = g_pMom + (size_t)i * (MCH * 56) + p;
        double s = 0.0;
#pragma unroll
        for (int c = 0; c < MCH; c++)
            s += (double)q[c * 56];
        sS[p] = s;
    }
    __syncthreads();

    if (t < 66) {
        int p = t, r = 0;
        while (p >= KB - r) { p -= KB - r; r++; }
        int cc = r + p;
        double v0 = 0.0, v1 = 0.0, v2 = 0.0, v3 = 0.0;
        for (int j = 0; j < 8; j++) {
            int a = r - j, b = cc - j;
            if (a >= 0 && a < 4 && b >= 0 && b < 4) {
#pragma unroll
                for (int q1 = 0; q1 < 4; q1++) {
                    double cb = CAD[b][q1];
                    v0 += CAD[a][0] * cb * sS[j * 7 + 0 + q1];
                    v1 += CAD[a][1] * cb * sS[j * 7 + 1 + q1];
                    v2 += CAD[a][2] * cb * sS[j * 7 + 2 + q1];
                    v3 += CAD[a][3] * cb * sS[j * 7 + 3 + q1];
                }
            }
        }
        sAtAd[t] = ((v0 + v1) + (v2 + v3)) / 36.0;
    }
    __syncthreads();

    // parallel-column Cholesky
    for (int j = 0; j < KB; j++) {
        if (t == 0) {
            float d = (float)sAtAd[tidx(j, j)];
            for (int m = 0; m < j; m++) { float v = sL[tidx(m, j)]; d -= v * v; }
            d = sqrtf(d);
            sL[tidx(j, j)] = d;
            sLinv[j] = 1.0f / d;
        }
        __syncthreads();
        if (t > j && t < KB) {
            float s = (float)sAtAd[tidx(j, t)];
            for (int m = 0; m < j; m++) s -= sL[tidx(m, t)] * sL[tidx(m, j)];
            sL[tidx(j, t)] = s * sLinv[j];
        }
        __syncthreads();
    }

    if (t < OUT_F) {
        const int o = t;
        float z[KB], X[KB];
#pragma unroll
        for (int r = 0; r < KB; r++) {
            float s = sAtB[r][o];
#pragma unroll
            for (int m = 0; m < KB; m++) if (m < r) s -= sL[tidx(m, r)] * z[m];
            z[r] = s * sLinv[r];
        }
#pragma unroll
        for (int r = KB - 1; r >= 0; r--) {
            float s = z[r];
#pragma unroll
            for (int m = KB - 1; m >= 0; m--) if (m > r) s -= sL[tidx(r, m)] * X[m];
            X[r] = s * sLinv[r];
            out[(size_t)o * (IN_F * KB) + i * KB + r] = X[r];
        }
    }
}

extern "C" void kernel_launch(void* const* d_in, const int* in_sizes, int n_in,
                              void* d_out, int out_size) {
    const float* x = (const float*)d_in[0];
    const float* y = (const float*)d_in[1];
    (void)n_in; (void)out_size;
    float* out = (float*)d_out;
    int N = in_sizes[0] / IN_F;

    cudaFuncSetAttribute(accum_kernel,
                         cudaFuncAttributeMaxDynamicSharedMemorySize,
                         SMEM_FLOATS * (int)sizeof(float));

    dim3 tgrid((N + 31) / 32, IN_F / 32);
    transpose_kernel<<<tgrid, dim3(32, 8)>>>(x, N);

    moments_kernel<<<dim3(MCH, IN_F), 256>>>(N);

    accum_kernel<<<dim3(NCH, 32), 256, SMEM_FLOATS * (int)sizeof(float)>>>(y, N);

    solve_kernel<<<IN_F, 256>>>(out);
}